// round 7
// baseline (speedup 1.0000x reference)
#include <cuda_runtime.h>
#include <cstdint>

#define CIN 3
#define COUT 16
#define HH 32
#define WW 32
#define OH 30
#define OW 30
#define RPITCH 36                 /* padded raw row: 36 floats (16B-aligned, bank-skewed) */

typedef unsigned long long u64;

// ---- f32x2 packed-math helpers ----
__device__ __forceinline__ u64 pk2(float a, float b) {
    u64 r; asm("mov.b64 %0, {%1, %2};" : "=l"(r) : "f"(a), "f"(b)); return r;
}
__device__ __forceinline__ u64 dup2(float a) {
    u64 r; asm("mov.b64 %0, {%1, %1};" : "=l"(r) : "f"(a)); return r;
}
__device__ __forceinline__ u64 fma2(u64 a, u64 b, u64 c) {
    u64 d; asm("fma.rn.f32x2 %0, %1, %2, %3;" : "=l"(d) : "l"(a), "l"(b), "l"(c)); return d;
}
__device__ __forceinline__ u64 mul2(u64 a, u64 b) {
    u64 d; asm("mul.rn.f32x2 %0, %1, %2;" : "=l"(d) : "l"(a), "l"(b)); return d;
}
__device__ __forceinline__ u64 add2(u64 a, u64 b) {
    u64 d; asm("add.rn.f32x2 %0, %1, %2;" : "=l"(d) : "l"(a), "l"(b)); return d;
}
__device__ __forceinline__ void upk2(u64 v, float& a, float& b) {
    asm("mov.b64 {%0, %1}, %2;" : "=f"(a), "=f"(b) : "l"(v));
}
// activation: relu(v) * min(v+3,6)/6 == max(v,0) * min(v/6+0.5, 1)
__device__ __forceinline__ float hswish_relu(float v, float t) {
    return fmaxf(v, 0.0f) * fminf(t, 1.0f);
}

// 1D Winograd F(4,3) input-transform (B^T apply), 6 in -> 6 out.
__device__ __forceinline__ void btrans6(const float v[6], float e[6]) {
    float a  = fmaf(v[2], -4.0f, v[4]);   // v4 - 4 v2
    float b  = fmaf(v[1], -4.0f, v[3]);   // v3 - 4 v1
    float c_ = v[4] - v[2];
    float dl = v[3] - v[1];
    e[0] = fmaf(v[0], 4.0f, fmaf(v[2], -5.0f, v[4]));
    e[1] = a + b;
    e[2] = a - b;
    e[3] = fmaf(dl,  2.0f, c_);
    e[4] = fmaf(dl, -2.0f, c_);
    e[5] = fmaf(v[1], 4.0f, fmaf(v[3], -5.0f, v[5]));
}

// 1D weight transform (G apply), 3 in -> 6 out.
__device__ __forceinline__ void gtrans3(float g0, float g1, float g2, float w[6]) {
    w[0] = 0.25f * g0;
    w[1] = (g0 + g1 + g2) * (-1.0f / 6.0f);
    w[2] = (g1 - g0 - g2) * (1.0f / 6.0f);
    w[3] = g0 * (1.0f / 24.0f) + g1 * (1.0f / 12.0f) + g2 * (1.0f / 6.0f);
    w[4] = g0 * (1.0f / 24.0f) - g1 * (1.0f / 12.0f) + g2 * (1.0f / 6.0f);
    w[5] = g2;
}

// Winograd F(4x4,3x3), fp32, channel-pairs packed in f32x2.
// One block = one image, 256 threads = 8 warps = 8 output-channel pairs.
// Tile grid: 8x8 tiles, origins {0,4,8,12,16,20,24,26}^2 (last tile overlaps;
// stores are masked so every output pixel is written exactly once).
__global__ void __launch_bounds__(256, 2) conv3x3_hswish_wino(
    const float* __restrict__ x,
    const float* __restrict__ wgt,
    const float* __restrict__ bias,
    float* __restrict__ out)
{
    __shared__ __align__(16) float rawf[CIN * HH * RPITCH];   // 13824 B
    __shared__ __align__(16) float uf[36 * CIN * 64];         // 27648 B  [k][ci][tile]
    __shared__ __align__(16) float wtf[36 * CIN * COUT];      // 6912 B   [k][ci][co]

    const int n   = blockIdx.x;
    const int tid = threadIdx.x;

    // ---------- P1: load image into padded raw smem ----------
    {
        const float4* src = reinterpret_cast<const float4*>(x + (size_t)n * (CIN * HH * WW));
        #pragma unroll
        for (int kq = 0; kq < 3; kq++) {
            const int i   = tid + kq * 256;        // 0..767 float4 units
            const int ci  = i >> 8;
            const int rem = i & 255;
            const int yy  = rem >> 3;
            const int x4  = rem & 7;
            float4 f = src[i];
            float* dp = rawf + ci * (HH * RPITCH) + yy * RPITCH + x4 * 4;
            dp[0] = f.x; dp[1] = f.y; dp[2] = f.z; dp[3] = f.w;
        }
    }

    // ---------- P2: weight transform (48 threads; independent of P1) ----------
    if (tid < CIN * COUT) {
        const int co = tid & 15;
        const int ci = tid >> 4;
        const float* g = wgt + co * 27 + ci * 9;
        // Gg : 6x3 (columns transformed by G)
        float h[6][3];
        #pragma unroll
        for (int c = 0; c < 3; c++) {
            float w6[6];
            gtrans3(g[0 * 3 + c], g[1 * 3 + c], g[2 * 3 + c], w6);
            #pragma unroll
            for (int r = 0; r < 6; r++) h[r][c] = w6[r];
        }
        // (Gg) G^T : 6x6 (rows transformed by G)
        #pragma unroll
        for (int r = 0; r < 6; r++) {
            float w6[6];
            gtrans3(h[r][0], h[r][1], h[r][2], w6);
            #pragma unroll
            for (int q = 0; q < 6; q++)
                wtf[(r * 6 + q) * (CIN * COUT) + ci * COUT + co] = w6[q];
        }
    }
    __syncthreads();

    // ---------- P3: input transform, 192 units = (ci, tile) ----------
    if (tid < CIN * 64) {
        const int ci   = tid >> 6;
        const int tile = tid & 63;
        const int ty6  = tile >> 3, tx6 = tile & 7;
        const int oy   = min(ty6 * 4, 26);
        const int ox   = min(tx6 * 4, 26);
        const float* rb = rawf + ci * (HH * RPITCH) + oy * RPITCH + ox;

        float d[6][6], T[6][6];
        #pragma unroll
        for (int r = 0; r < 6; r++)
            #pragma unroll
            for (int c = 0; c < 6; c++)
                d[r][c] = rb[r * RPITCH + c];

        // columns: combine over row index (B^T d)
        #pragma unroll
        for (int c = 0; c < 6; c++) {
            float vin[6], e[6];
            #pragma unroll
            for (int r = 0; r < 6; r++) vin[r] = d[r][c];
            btrans6(vin, e);
            #pragma unroll
            for (int r = 0; r < 6; r++) T[r][c] = e[r];
        }
        // rows: combine over col index ((B^T d) B)
        #pragma unroll
        for (int r = 0; r < 6; r++) {
            float e[6];
            btrans6(T[r], e);
            #pragma unroll
            for (int c = 0; c < 6; c++)
                uf[(r * 6 + c) * (CIN * 64) + ci * 64 + tile] = e[c];
        }
    }
    __syncthreads();

    // ---------- P4: eltwise + output transform ----------
    const int warp = tid >> 5;
    const int lane = tid & 31;
    const int c0   = warp * 2;                  // channel pair

    const u64 bp     = pk2(bias[c0], bias[c0 + 1]);
    const u64 negone = dup2(-1.0f);
    const u64 two    = dup2(2.0f);
    const u64 four   = dup2(4.0f);
    const u64 eight  = dup2(8.0f);
    const u64 sixth  = dup2(1.0f / 6.0f);
    const u64 half   = dup2(0.5f);

    float* outp = out + ((size_t)n * COUT + c0) * (OH * OW);

    #pragma unroll
    for (int it = 0; it < 2; it++) {
        const int tile = it * 32 + lane;
        const int ty6  = tile >> 3, tx6 = tile & 7;
        const int oy   = min(ty6 * 4, 26);
        const int ox   = min(tx6 * 4, 26);

        u64 z[4][6];

        #pragma unroll
        for (int cq = 0; cq < 6; cq++) {
            u64 m[6];
            #pragma unroll
            for (int kr = 0; kr < 6; kr++) {
                const int k = kr * 6 + cq;
                const float u0 = uf[k * (CIN * 64) + 0 * 64 + tile];
                const float u1 = uf[k * (CIN * 64) + 1 * 64 + tile];
                const float u2 = uf[k * (CIN * 64) + 2 * 64 + tile];
                const u64 w0 = *reinterpret_cast<const u64*>(&wtf[k * (CIN * COUT) + 0 * COUT + c0]);
                const u64 w1 = *reinterpret_cast<const u64*>(&wtf[k * (CIN * COUT) + 1 * COUT + c0]);
                const u64 w2 = *reinterpret_cast<const u64*>(&wtf[k * (CIN * COUT) + 2 * COUT + c0]);
                m[kr] = fma2(dup2(u2), w2, fma2(dup2(u1), w1, mul2(dup2(u0), w0)));
            }
            // z = A^T m  (combine over rows)
            const u64 s1 = add2(m[1], m[2]);
            const u64 s2 = fma2(m[2], negone, m[1]);
            const u64 s3 = add2(m[3], m[4]);
            const u64 s4 = fma2(m[4], negone, m[3]);
            z[0][cq] = add2(add2(m[0], s1), s3);
            z[1][cq] = fma2(s4, two, s2);
            z[2][cq] = fma2(s3, four, s1);
            z[3][cq] = add2(fma2(s4, eight, s2), m[5]);
        }

        const bool row_full = (oy != 24);       // oy==24 tile owns rows 24,25 only
        const bool col_full = (ox != 24);       // ox==24 tile owns cols 24,25 only

        #pragma unroll
        for (int r = 0; r < 4; r++) {
            if (!row_full && r >= 2) break;
            // o = z[r] * A  (combine over cols)
            const u64 s1 = add2(z[r][1], z[r][2]);
            const u64 s2 = fma2(z[r][2], negone, z[r][1]);
            const u64 s3 = add2(z[r][3], z[r][4]);
            const u64 s4 = fma2(z[r][4], negone, z[r][3]);
            u64 o[4];
            o[0] = add2(add2(z[r][0], s1), s3);
            o[1] = fma2(s4, two, s2);
            o[2] = fma2(s3, four, s1);
            o[3] = add2(fma2(s4, eight, s2), z[r][5]);

            float a0[4], a1[4];
            #pragma unroll
            for (int j = 0; j < 4; j++) {
                const u64 v = add2(o[j], bp);
                const u64 t = fma2(v, sixth, half);
                float v0, v1, t0, t1;
                upk2(v, v0, v1);
                upk2(t, t0, t1);
                a0[j] = hswish_relu(v0, t0);
                a1[j] = hswish_relu(v1, t1);
            }

            float* p0 = outp + (oy + r) * OW + ox;           // channel c0
            float* p1 = p0 + OH * OW;                        // channel c0+1
            *reinterpret_cast<float2*>(p0) = make_float2(a0[0], a0[1]);
            *reinterpret_cast<float2*>(p1) = make_float2(a1[0], a1[1]);
            if (col_full) {
                *reinterpret_cast<float2*>(p0 + 2) = make_float2(a0[2], a0[3]);
                *reinterpret_cast<float2*>(p1 + 2) = make_float2(a1[2], a1[3]);
            }
        }
    }
}

extern "C" void kernel_launch(void* const* d_in, const int* in_sizes, int n_in,
                              void* d_out, int out_size) {
    const float* x = (const float*)d_in[0];
    const float* w = (const float*)d_in[1];
    const float* b = (const float*)d_in[2];
    float* out = (float*)d_out;

    const int N = in_sizes[0] / (CIN * HH * WW);   // 4096
    conv3x3_hswish_wino<<<N, 256>>>(x, w, b, out);
}

// round 8
// speedup vs baseline: 1.1555x; 1.1555x over previous
#include <cuda_runtime.h>
#include <cstdint>

#define CIN 3
#define COUT 16
#define HH 32
#define WW 32
#define OH 30
#define OW 30
#define RPITCH 36

typedef unsigned long long u64;

// ---- f32x2 packed-math helpers ----
__device__ __forceinline__ u64 pk2(float a, float b) {
    u64 r; asm("mov.b64 %0, {%1, %2};" : "=l"(r) : "f"(a), "f"(b)); return r;
}
__device__ __forceinline__ u64 dup2(float a) {
    u64 r; asm("mov.b64 %0, {%1, %1};" : "=l"(r) : "f"(a)); return r;
}
__device__ __forceinline__ u64 fma2(u64 a, u64 b, u64 c) {
    u64 d; asm("fma.rn.f32x2 %0, %1, %2, %3;" : "=l"(d) : "l"(a), "l"(b), "l"(c)); return d;
}
__device__ __forceinline__ u64 mul2(u64 a, u64 b) {
    u64 d; asm("mul.rn.f32x2 %0, %1, %2;" : "=l"(d) : "l"(a), "l"(b)); return d;
}
__device__ __forceinline__ u64 add2(u64 a, u64 b) {
    u64 d; asm("add.rn.f32x2 %0, %1, %2;" : "=l"(d) : "l"(a), "l"(b)); return d;
}
__device__ __forceinline__ void upk2(u64 v, float& a, float& b) {
    asm("mov.b64 {%0, %1}, %2;" : "=f"(a), "=f"(b) : "l"(v));
}
__device__ __forceinline__ float hswish_relu(float v, float t) {
    return fmaxf(v, 0.0f) * fminf(t, 1.0f);
}

// 1D Winograd F(4,3) input transform (B^T apply), 6 -> 6.
__device__ __forceinline__ void btrans6(const float v[6], float e[6]) {
    float a  = fmaf(v[2], -4.0f, v[4]);
    float b  = fmaf(v[1], -4.0f, v[3]);
    float c_ = v[4] - v[2];
    float dl = v[3] - v[1];
    e[0] = fmaf(v[0], 4.0f, fmaf(v[2], -5.0f, v[4]));
    e[1] = a + b;
    e[2] = a - b;
    e[3] = fmaf(dl,  2.0f, c_);
    e[4] = fmaf(dl, -2.0f, c_);
    e[5] = fmaf(v[1], 4.0f, fmaf(v[3], -5.0f, v[5]));
}
// 1D weight transform (G apply), 3 -> 6.
__device__ __forceinline__ void gtrans3(float g0, float g1, float g2, float w[6]) {
    w[0] = 0.25f * g0;
    w[1] = (g0 + g1 + g2) * (-1.0f / 6.0f);
    w[2] = (g1 - g0 - g2) * (1.0f / 6.0f);
    w[3] = g0 * (1.0f / 24.0f) + g1 * (1.0f / 12.0f) + g2 * (1.0f / 6.0f);
    w[4] = g0 * (1.0f / 24.0f) - g1 * (1.0f / 12.0f) + g2 * (1.0f / 6.0f);
    w[5] = g2;
}

// Winograd F(4x4,3x3) v2.
// Grid 8192: block b -> image b>>1, channel-half b&1 (8 channels = 4 pairs).
// Block 128 threads = 4 warps; warp = one channel pair; lane = tile (2 iters
// cover the 8x8 tile grid, origins {0,4,...,24,26}, masked stores).
// smem 44.9KB -> 4 blocks/SM (16 warps). Weights per kr-pair via one broadcast
// LDS.128. Register peak ~107 (< the 128 cap -> no spills, unlike R7).
__global__ void __launch_bounds__(128, 4) conv3x3_hswish_wino2(
    const float* __restrict__ x,
    const float* __restrict__ wgt,
    const float* __restrict__ bias,
    float* __restrict__ out)
{
    __shared__ __align__(16) float rawf[CIN * HH * RPITCH];   // 13824 B
    __shared__ __align__(16) float uf[36 * CIN * 64];         // 27648 B  [k][ci*64+tile]
    __shared__ __align__(16) u64   wtf[CIN * 4 * 36];         // 3456 B   [ci][p][cq][kr]

    const int n    = blockIdx.x >> 1;
    const int half = blockIdx.x & 1;
    const int tid  = threadIdx.x;

    // ---------- P1: image -> padded raw smem ----------
    {
        const float4* src = reinterpret_cast<const float4*>(x + (size_t)n * (CIN * HH * WW));
        #pragma unroll
        for (int kq = 0; kq < 6; kq++) {
            const int i   = tid + kq * 128;       // 0..767
            const int ci  = i >> 8;
            const int rem = i & 255;
            const int yy  = rem >> 3;
            const int x4  = rem & 7;
            float4 f = src[i];
            float* dp = rawf + ci * (HH * RPITCH) + yy * RPITCH + x4 * 4;
            dp[0] = f.x; dp[1] = f.y; dp[2] = f.z; dp[3] = f.w;
        }
    }

    // ---------- P2: weight transform for this block's 8 channels ----------
    if (tid < 24) {
        const int co_l = tid & 7;                 // local channel 0..7
        const int ci   = tid >> 3;
        const int co   = half * 8 + co_l;
        const int p    = co_l >> 1;               // local pair
        const int ln   = co_l & 1;                // lane within pair
        const float* g = wgt + co * 27 + ci * 9;
        float h[6][3];
        #pragma unroll
        for (int c = 0; c < 3; c++) {
            float w6[6];
            gtrans3(g[0 * 3 + c], g[1 * 3 + c], g[2 * 3 + c], w6);
            #pragma unroll
            for (int r = 0; r < 6; r++) h[r][c] = w6[r];
        }
        float* wf = reinterpret_cast<float*>(wtf);
        #pragma unroll
        for (int r = 0; r < 6; r++) {             // r = kr
            float w6[6];
            gtrans3(h[r][0], h[r][1], h[r][2], w6);
            #pragma unroll
            for (int q = 0; q < 6; q++)           // q = cq
                wf[(((ci * 4 + p) * 6 + q) * 6 + r) * 2 + ln] = w6[q];
        }
    }
    __syncthreads();

    // ---------- P3: input transform, 192 units over 2 rounds ----------
    #pragma unroll
    for (int rd = 0; rd < 2; rd++) {
        const int u = tid + rd * 128;
        if (u < CIN * 64) {
            const int ci   = u >> 6;
            const int tile = u & 63;
            const int ty6  = tile >> 3, tx6 = tile & 7;
            const int oy   = min(ty6 * 4, 26);
            const int ox   = min(tx6 * 4, 26);
            const float* rb = rawf + ci * (HH * RPITCH) + oy * RPITCH + ox;

            float d[6][6], T[6][6];
            #pragma unroll
            for (int r = 0; r < 6; r++)
                #pragma unroll
                for (int c = 0; c < 6; c++)
                    d[r][c] = rb[r * RPITCH + c];
            #pragma unroll
            for (int c = 0; c < 6; c++) {
                float vin[6], e[6];
                #pragma unroll
                for (int r = 0; r < 6; r++) vin[r] = d[r][c];
                btrans6(vin, e);
                #pragma unroll
                for (int r = 0; r < 6; r++) T[r][c] = e[r];
            }
            #pragma unroll
            for (int r = 0; r < 6; r++) {
                float e[6];
                btrans6(T[r], e);
                #pragma unroll
                for (int c = 0; c < 6; c++)
                    uf[(r * 6 + c) * (CIN * 64) + ci * 64 + tile] = e[c];
            }
        }
    }
    __syncthreads();

    // ---------- P4: eltwise + output transform ----------
    const int warp = tid >> 5;                    // = local pair p
    const int lane = tid & 31;
    const int p    = warp;
    const int c0   = half * 8 + p * 2;

    const u64 bp     = pk2(bias[c0], bias[c0 + 1]);
    const u64 negone = dup2(-1.0f);
    const u64 two    = dup2(2.0f);
    const u64 four   = dup2(4.0f);
    const u64 eight  = dup2(8.0f);
    const u64 sixth  = dup2(1.0f / 6.0f);
    const u64 half2  = dup2(0.5f);

    float* outp = out + ((size_t)n * COUT + c0) * (OH * OW);

    #pragma unroll
    for (int it = 0; it < 2; it++) {
        const int tile = it * 32 + lane;
        const int ty6  = tile >> 3, tx6 = tile & 7;
        const int oy   = min(ty6 * 4, 26);
        const int ox   = min(tx6 * 4, 26);

        u64 z[4][6];

        #pragma unroll
        for (int cq = 0; cq < 6; cq++) {
            u64 m[6];
            #pragma unroll
            for (int krp = 0; krp < 3; krp++) {
                const int kr = krp * 2;
                // broadcast weight pair-of-pairs for (kr, kr+1), all 3 ci
                const ulonglong2 w0 = *reinterpret_cast<const ulonglong2*>(
                    &wtf[((0 * 4 + p) * 6 + cq) * 6 + kr]);
                const ulonglong2 w1 = *reinterpret_cast<const ulonglong2*>(
                    &wtf[((1 * 4 + p) * 6 + cq) * 6 + kr]);
                const ulonglong2 w2 = *reinterpret_cast<const ulonglong2*>(
                    &wtf[((2 * 4 + p) * 6 + cq) * 6 + kr]);
                const int k0 = kr * 6 + cq;
                const int k1 = k0 + 6;
                const float u00 = uf[k0 * (CIN * 64) + 0 * 64 + tile];
                const float u01 = uf[k0 * (CIN * 64) + 1 * 64 + tile];
                const float u02 = uf[k0 * (CIN * 64) + 2 * 64 + tile];
                const float u10 = uf[k1 * (CIN * 64) + 0 * 64 + tile];
                const float u11 = uf[k1 * (CIN * 64) + 1 * 64 + tile];
                const float u12 = uf[k1 * (CIN * 64) + 2 * 64 + tile];
                m[kr]     = fma2(dup2(u02), w2.x, fma2(dup2(u01), w1.x, mul2(dup2(u00), w0.x)));
                m[kr + 1] = fma2(dup2(u12), w2.y, fma2(dup2(u11), w1.y, mul2(dup2(u10), w0.y)));
            }
            // z[:, cq] = A^T m
            const u64 s1 = add2(m[1], m[2]);
            const u64 s2 = fma2(m[2], negone, m[1]);
            const u64 s3 = add2(m[3], m[4]);
            const u64 s4 = fma2(m[4], negone, m[3]);
            z[0][cq] = add2(add2(m[0], s1), s3);
            z[1][cq] = fma2(s4, two, s2);
            z[2][cq] = fma2(s3, four, s1);
            z[3][cq] = add2(fma2(s4, eight, s2), m[5]);
        }

        const bool row_full = (oy != 24);
        const bool col_full = (ox != 24);

        #pragma unroll
        for (int r = 0; r < 4; r++) {
            if (!row_full && r >= 2) break;
            const u64 s1 = add2(z[r][1], z[r][2]);
            const u64 s2 = fma2(z[r][2], negone, z[r][1]);
            const u64 s3 = add2(z[r][3], z[r][4]);
            const u64 s4 = fma2(z[r][4], negone, z[r][3]);
            u64 o[4];
            o[0] = add2(add2(z[r][0], s1), s3);
            o[1] = fma2(s4, two, s2);
            o[2] = fma2(s3, four, s1);
            o[3] = add2(fma2(s4, eight, s2), z[r][5]);

            float a0[4], a1[4];
            #pragma unroll
            for (int j = 0; j < 4; j++) {
                const u64 v = add2(o[j], bp);
                const u64 t = fma2(v, sixth, half2);
                float v0, v1, t0, t1;
                upk2(v, v0, v1);
                upk2(t, t0, t1);
                a0[j] = hswish_relu(v0, t0);
                a1[j] = hswish_relu(v1, t1);
            }

            float* p0 = outp + (oy + r) * OW + ox;
            float* p1 = p0 + OH * OW;
            *reinterpret_cast<float2*>(p0) = make_float2(a0[0], a0[1]);
            *reinterpret_cast<float2*>(p1) = make_float2(a1[0], a1[1]);
            if (col_full) {
                *reinterpret_cast<float2*>(p0 + 2) = make_float2(a0[2], a0[3]);
                *reinterpret_cast<float2*>(p1 + 2) = make_float2(a1[2], a1[3]);
            }
        }
    }
}

extern "C" void kernel_launch(void* const* d_in, const int* in_sizes, int n_in,
                              void* d_out, int out_size) {
    const float* x = (const float*)d_in[0];
    const float* w = (const float*)d_in[1];
    const float* b = (const float*)d_in[2];
    float* out = (float*)d_out;

    const int N = in_sizes[0] / (CIN * HH * WW);   // 4096
    conv3x3_hswish_wino2<<<N * 2, 128>>>(x, w, b, out);
}

// round 9
// speedup vs baseline: 1.1813x; 1.0224x over previous
#include <cuda_runtime.h>
#include <cstdint>

#define CIN 3
#define COUT 16
#define HH 32
#define WW 32
#define OH 30
#define OW 30
#define RPITCH 36

typedef unsigned long long u64;

// ---- f32x2 packed-math helpers ----
__device__ __forceinline__ u64 pk2(float a, float b) {
    u64 r; asm("mov.b64 %0, {%1, %2};" : "=l"(r) : "f"(a), "f"(b)); return r;
}
__device__ __forceinline__ u64 dup2(float a) {
    u64 r; asm("mov.b64 %0, {%1, %1};" : "=l"(r) : "f"(a)); return r;
}
__device__ __forceinline__ u64 fma2(u64 a, u64 b, u64 c) {
    u64 d; asm("fma.rn.f32x2 %0, %1, %2, %3;" : "=l"(d) : "l"(a), "l"(b), "l"(c)); return d;
}
__device__ __forceinline__ u64 mul2(u64 a, u64 b) {
    u64 d; asm("mul.rn.f32x2 %0, %1, %2;" : "=l"(d) : "l"(a), "l"(b)); return d;
}
__device__ __forceinline__ u64 add2(u64 a, u64 b) {
    u64 d; asm("add.rn.f32x2 %0, %1, %2;" : "=l"(d) : "l"(a), "l"(b)); return d;
}
__device__ __forceinline__ void upk2(u64 v, float& a, float& b) {
    asm("mov.b64 {%0, %1}, %2;" : "=f"(a), "=f"(b) : "l"(v));
}
__device__ __forceinline__ float hswish_relu(float v, float t) {
    return fmaxf(v, 0.0f) * fminf(t, 1.0f);
}

// 1D Winograd F(4,3) input transform (B^T apply), 6 -> 6.
__device__ __forceinline__ void btrans6(const float v[6], float e[6]) {
    float a  = fmaf(v[2], -4.0f, v[4]);
    float b  = fmaf(v[1], -4.0f, v[3]);
    float c_ = v[4] - v[2];
    float dl = v[3] - v[1];
    e[0] = fmaf(v[0], 4.0f, fmaf(v[2], -5.0f, v[4]));
    e[1] = a + b;
    e[2] = a - b;
    e[3] = fmaf(dl,  2.0f, c_);
    e[4] = fmaf(dl, -2.0f, c_);
    e[5] = fmaf(v[1], 4.0f, fmaf(v[3], -5.0f, v[5]));
}
// 1D weight transform (G apply), 3 -> 6.
__device__ __forceinline__ void gtrans3(float g0, float g1, float g2, float w[6]) {
    w[0] = 0.25f * g0;
    w[1] = (g0 + g1 + g2) * (-1.0f / 6.0f);
    w[2] = (g1 - g0 - g2) * (1.0f / 6.0f);
    w[3] = g0 * (1.0f / 24.0f) + g1 * (1.0f / 12.0f) + g2 * (1.0f / 6.0f);
    w[4] = g0 * (1.0f / 24.0f) - g1 * (1.0f / 12.0f) + g2 * (1.0f / 6.0f);
    w[5] = g2;
}

// Winograd F(4x4,3x3) v3. One block = one image, 128 threads = 4 warps.
// occ 3 -> 170-reg cap (spill-free; R7/R8 died at the 128 cap).
// P4: warp handles pairs {warp, warp+4} sequentially; lane = tile (2 iters,
// origins {0,4,...,24,26}^2, masked stores). u-values software-pipelined one
// cq ahead through parity register buffers.
__global__ void __launch_bounds__(128, 3) conv3x3_hswish_wino3(
    const float* __restrict__ x,
    const float* __restrict__ wgt,
    const float* __restrict__ bias,
    float* __restrict__ out)
{
    __shared__ __align__(16) float rawf[CIN * HH * RPITCH];   // 13824 B
    __shared__ __align__(16) float uf[36 * CIN * 64];         // 27648 B  [k][ci*64+tile]
    __shared__ __align__(16) u64   wtf[CIN * 8 * 36];         // 6912 B   [ci][p][cq][kr]

    const int n   = blockIdx.x;
    const int tid = threadIdx.x;

    // ---------- P1: image -> padded raw smem (float4 in, float4 out) ----------
    {
        const float4* src = reinterpret_cast<const float4*>(x + (size_t)n * (CIN * HH * WW));
        #pragma unroll
        for (int kq = 0; kq < 6; kq++) {
            const int i   = tid + kq * 128;       // 0..767
            const int ci  = i >> 8;
            const int rem = i & 255;
            const int yy  = rem >> 3;
            const int x4  = rem & 7;
            *reinterpret_cast<float4*>(rawf + ci * (HH * RPITCH) + yy * RPITCH + x4 * 4) = src[i];
        }
    }

    // ---------- P2: weight transform, all 16 channels (48 threads) ----------
    if (tid < CIN * COUT) {
        const int co = tid & 15;
        const int ci = tid >> 4;
        const int p  = co >> 1;
        const int ln = co & 1;
        const float* g = wgt + co * 27 + ci * 9;
        float h[6][3];
        #pragma unroll
        for (int c = 0; c < 3; c++) {
            float w6[6];
            gtrans3(g[0 * 3 + c], g[1 * 3 + c], g[2 * 3 + c], w6);
            #pragma unroll
            for (int r = 0; r < 6; r++) h[r][c] = w6[r];
        }
        float* wf = reinterpret_cast<float*>(wtf);
        #pragma unroll
        for (int r = 0; r < 6; r++) {             // r = kr
            float w6[6];
            gtrans3(h[r][0], h[r][1], h[r][2], w6);
            #pragma unroll
            for (int q = 0; q < 6; q++)           // q = cq
                wf[(((ci * 8 + p) * 6 + q) * 6 + r) * 2 + ln] = w6[q];
        }
    }
    __syncthreads();

    // ---------- P3: input transform, 192 (ci,tile) units over 2 rounds ----------
    #pragma unroll
    for (int rd = 0; rd < 2; rd++) {
        const int u = tid + rd * 128;
        if (u < CIN * 64) {
            const int ci   = u >> 6;
            const int tile = u & 63;
            const int ty6  = tile >> 3, tx6 = tile & 7;
            const int oy   = min(ty6 * 4, 26);
            const int ox   = min(tx6 * 4, 26);
            const float* rb = rawf + ci * (HH * RPITCH) + oy * RPITCH + ox;

            float d[6][6], T[6][6];
            #pragma unroll
            for (int r = 0; r < 6; r++) {         // 8B-aligned vector loads
                const float2 q0 = *reinterpret_cast<const float2*>(rb + r * RPITCH + 0);
                const float2 q1 = *reinterpret_cast<const float2*>(rb + r * RPITCH + 2);
                const float2 q2 = *reinterpret_cast<const float2*>(rb + r * RPITCH + 4);
                d[r][0] = q0.x; d[r][1] = q0.y;
                d[r][2] = q1.x; d[r][3] = q1.y;
                d[r][4] = q2.x; d[r][5] = q2.y;
            }
            #pragma unroll
            for (int c = 0; c < 6; c++) {
                float vin[6], e[6];
                #pragma unroll
                for (int r = 0; r < 6; r++) vin[r] = d[r][c];
                btrans6(vin, e);
                #pragma unroll
                for (int r = 0; r < 6; r++) T[r][c] = e[r];
            }
            #pragma unroll
            for (int r = 0; r < 6; r++) {
                float e[6];
                btrans6(T[r], e);
                #pragma unroll
                for (int c = 0; c < 6; c++)
                    uf[(r * 6 + c) * (CIN * 64) + ci * 64 + tile] = e[c];
            }
        }
    }
    __syncthreads();

    // ---------- P4: eltwise + output transform ----------
    const int warp = tid >> 5;
    const int lane = tid & 31;

    const u64 negone = dup2(-1.0f);
    const u64 two    = dup2(2.0f);
    const u64 four   = dup2(4.0f);
    const u64 eight  = dup2(8.0f);
    const u64 sixth  = dup2(1.0f / 6.0f);
    const u64 half2  = dup2(0.5f);

    #pragma unroll 1
    for (int ppi = 0; ppi < 2; ppi++) {
        const int p  = warp + ppi * 4;
        const int c0 = p * 2;
        const u64 bp = pk2(bias[c0], bias[c0 + 1]);
        float* outp  = out + ((size_t)n * COUT + c0) * (OH * OW);

        #pragma unroll 1
        for (int it = 0; it < 2; it++) {
            const int tile = it * 32 + lane;
            const int ty6  = tile >> 3, tx6 = tile & 7;
            const int oy   = min(ty6 * 4, 26);
            const int ox   = min(tx6 * 4, 26);

            u64 z[4][6];
            float ua[18], ub[18];   // parity u buffers, [kr*3 + ci]

            // preload cq = 0
            #pragma unroll
            for (int kr = 0; kr < 6; kr++)
                #pragma unroll
                for (int ci = 0; ci < 3; ci++)
                    ua[kr * 3 + ci] = uf[(kr * 6 + 0) * (CIN * 64) + ci * 64 + tile];

            #pragma unroll
            for (int cq = 0; cq < 6; cq++) {
                const float* cur = (cq & 1) ? ub : ua;
                float*       nxt = (cq & 1) ? ua : ub;
                if (cq < 5) {   // prefetch next cq's u values
                    #pragma unroll
                    for (int kr = 0; kr < 6; kr++)
                        #pragma unroll
                        for (int ci = 0; ci < 3; ci++)
                            nxt[kr * 3 + ci] = uf[(kr * 6 + cq + 1) * (CIN * 64) + ci * 64 + tile];
                }

                u64 m[6];
                #pragma unroll
                for (int krp = 0; krp < 3; krp++) {
                    const int kr = krp * 2;
                    const ulonglong2 w0 = *reinterpret_cast<const ulonglong2*>(
                        &wtf[((0 * 8 + p) * 6 + cq) * 6 + kr]);
                    const ulonglong2 w1 = *reinterpret_cast<const ulonglong2*>(
                        &wtf[((1 * 8 + p) * 6 + cq) * 6 + kr]);
                    const ulonglong2 w2 = *reinterpret_cast<const ulonglong2*>(
                        &wtf[((2 * 8 + p) * 6 + cq) * 6 + kr]);
                    m[kr]     = fma2(dup2(cur[kr * 3 + 2]), w2.x,
                                fma2(dup2(cur[kr * 3 + 1]), w1.x,
                                mul2(dup2(cur[kr * 3 + 0]), w0.x)));
                    m[kr + 1] = fma2(dup2(cur[(kr + 1) * 3 + 2]), w2.y,
                                fma2(dup2(cur[(kr + 1) * 3 + 1]), w1.y,
                                mul2(dup2(cur[(kr + 1) * 3 + 0]), w0.y)));
                }
                // z[:, cq] = A^T m
                const u64 s1 = add2(m[1], m[2]);
                const u64 s2 = fma2(m[2], negone, m[1]);
                const u64 s3 = add2(m[3], m[4]);
                const u64 s4 = fma2(m[4], negone, m[3]);
                z[0][cq] = add2(add2(m[0], s1), s3);
                z[1][cq] = fma2(s4, two, s2);
                z[2][cq] = fma2(s3, four, s1);
                z[3][cq] = add2(fma2(s4, eight, s2), m[5]);
            }

            const bool row_full = (oy != 24);
            const bool col_full = (ox != 24);

            #pragma unroll
            for (int r = 0; r < 4; r++) {
                if (!row_full && r >= 2) break;
                const u64 s1 = add2(z[r][1], z[r][2]);
                const u64 s2 = fma2(z[r][2], negone, z[r][1]);
                const u64 s3 = add2(z[r][3], z[r][4]);
                const u64 s4 = fma2(z[r][4], negone, z[r][3]);
                u64 o[4];
                o[0] = add2(add2(z[r][0], s1), s3);
                o[1] = fma2(s4, two, s2);
                o[2] = fma2(s3, four, s1);
                o[3] = add2(fma2(s4, eight, s2), z[r][5]);

                float a0[4], a1[4];
                #pragma unroll
                for (int j = 0; j < 4; j++) {
                    const u64 v = add2(o[j], bp);
                    const u64 t = fma2(v, sixth, half2);
                    float v0, v1, t0, t1;
                    upk2(v, v0, v1);
                    upk2(t, t0, t1);
                    a0[j] = hswish_relu(v0, t0);
                    a1[j] = hswish_relu(v1, t1);
                }

                float* p0 = outp + (oy + r) * OW + ox;
                float* p1 = p0 + OH * OW;
                *reinterpret_cast<float2*>(p0) = make_float2(a0[0], a0[1]);
                *reinterpret_cast<float2*>(p1) = make_float2(a1[0], a1[1]);
                if (col_full) {
                    *reinterpret_cast<float2*>(p0 + 2) = make_float2(a0[2], a0[3]);
                    *reinterpret_cast<float2*>(p1 + 2) = make_float2(a1[2], a1[3]);
                }
            }
        }
    }
}

extern "C" void kernel_launch(void* const* d_in, const int* in_sizes, int n_in,
                              void* d_out, int out_size) {
    const float* x = (const float*)d_in[0];
    const float* w = (const float*)d_in[1];
    const float* b = (const float*)d_in[2];
    float* out = (float*)d_out;

    const int N = in_sizes[0] / (CIN * HH * WW);   // 4096
    conv3x3_hswish_wino3<<<N, 128>>>(x, w, b, out);
}

// round 10
// speedup vs baseline: 2.2746x; 1.9255x over previous
#include <cuda_runtime.h>
#include <cstdint>

#define CIN 3
#define COUT 16
#define HH 32
#define WW 32
#define OH 30
#define OW 30

typedef unsigned long long u64;

// ---- f32x2 packed-math helpers (SASS FFMA2 via PTX only) ----
__device__ __forceinline__ u64 pk2(float a, float b) {
    u64 r; asm("mov.b64 %0, {%1, %2};" : "=l"(r) : "f"(a), "f"(b)); return r;
}
__device__ __forceinline__ u64 fma2(u64 a, u64 b, u64 c) {
    u64 d; asm("fma.rn.f32x2 %0, %1, %2, %3;" : "=l"(d) : "l"(a), "l"(b), "l"(c)); return d;
}
__device__ __forceinline__ void upk2(u64 v, float& a, float& b) {
    asm("mov.b64 {%0, %1}, %2;" : "=f"(a), "=f"(b) : "l"(v));
}
// activation: relu(v) * min(v+3,6)/6 == max(v,0) * min(v/6+0.5, 1)
__device__ __forceinline__ float hswish_relu(float v) {
    return fmaxf(v, 0.0f) * fminf(fmaf(v, 1.0f / 6.0f, 0.5f), 1.0f);
}

// Direct conv v4. One block = one image, 128 threads = 4 warps.
// Warp w -> 4 output channels (4w..4w+3) as two f32x2 accumulator sets; lane =
// output column. Image lives in smem PRE-DUPLICATED as {v,v} u64 pairs: each
// window value is ONE LDS.64 straight into an FFMA2 operand (no dup MOVs).
// At 4ch/warp the crossbar demand (64k cyc/SM) stays under the fma-pipe demand
// (96k cyc/SM) — this is why R4's 2ch/warp variant was L1-bound and this is not.
// Streaming over input rows r: row r feeds output rows r (ky0), r-1 (ky1),
// r-2 (ky2). Fully unrolled; single cur[] buffer, ~150 regs (<170 cap) leaves
// ptxas headroom to hoist next-row loads into dead cur slots.
__global__ void __launch_bounds__(128, 3) conv3x3_hswish_kernel(
    const float* __restrict__ x,
    const float* __restrict__ wgt,
    const float* __restrict__ bias,
    float* __restrict__ out)
{
    __shared__ u64 s_in[CIN * HH * WW];   // dup pairs, 24 KB

    const int n   = blockIdx.x;
    const int tid = threadIdx.x;

    {   // coalesced load + duplicate: 768 float4 in -> 1536 float4 out
        const float4* src = reinterpret_cast<const float4*>(x + (size_t)n * (CIN * HH * WW));
        float4* dst = reinterpret_cast<float4*>(s_in);
        #pragma unroll
        for (int i = 0; i < 6; i++) {
            const int idx = tid + i * 128;
            float4 f = src[idx];
            dst[idx * 2 + 0] = make_float4(f.x, f.x, f.y, f.y);
            dst[idx * 2 + 1] = make_float4(f.z, f.z, f.w, f.w);
        }
    }
    __syncthreads();

    const int warp = tid >> 5;
    const int lane = tid & 31;
    const int c0   = warp * 4;

    // packed weights: wpA -> (c0, c0+1), wpB -> (c0+2, c0+3)
    u64 wpA[27], wpB[27];
    #pragma unroll
    for (int t = 0; t < 27; t++) {
        wpA[t] = pk2(wgt[(c0 + 0) * 27 + t], wgt[(c0 + 1) * 27 + t]);
        wpB[t] = pk2(wgt[(c0 + 2) * 27 + t], wgt[(c0 + 3) * 27 + t]);
    }
    const u64 bpA = pk2(bias[c0 + 0], bias[c0 + 1]);
    const u64 bpB = pk2(bias[c0 + 2], bias[c0 + 3]);

    if (lane >= OW) return;   // barrier done; lanes 30/31 retire

    const u64* base = s_in + lane;    // [ci*1024 + row*32 + kx]
    float* out0 = out + ((size_t)n * COUT + c0) * (OH * OW) + lane;

    u64 cur[9];               // current input row, dup pairs (LDS.64 each)
    u64 accA[3], accB[3];     // acc[y % 3] = accumulator for output row y

    #pragma unroll
    for (int r = 0; r < 32; r++) {
        // load input row r (ptxas hoists these into dead cur[] slots of the
        // previous iteration thanks to the full unroll)
        #pragma unroll
        for (int ci = 0; ci < CIN; ci++)
            #pragma unroll
            for (int kx = 0; kx < 3; kx++)
                cur[ci * 3 + kx] = base[ci * 1024 + r * 32 + kx];

        #pragma unroll
        for (int t = 0; t < 9; t++) {
            const int ci = t / 3, kx = t % 3;
            const u64 cv = cur[t];
            if (r >= 2) {
                accA[(r - 2) % 3] = fma2(cv, wpA[ci * 9 + 6 + kx], accA[(r - 2) % 3]);
                accB[(r - 2) % 3] = fma2(cv, wpB[ci * 9 + 6 + kx], accB[(r - 2) % 3]);
            }
            if (r >= 1 && r <= 30) {
                accA[(r - 1) % 3] = fma2(cv, wpA[ci * 9 + 3 + kx], accA[(r - 1) % 3]);
                accB[(r - 1) % 3] = fma2(cv, wpB[ci * 9 + 3 + kx], accB[(r - 1) % 3]);
            }
            if (r <= 29) {
                // first tap of output row r: accumulator starts at bias
                if (t == 0) {
                    accA[r % 3] = fma2(cv, wpA[ci * 9 + 0 + kx], bpA);
                    accB[r % 3] = fma2(cv, wpB[ci * 9 + 0 + kx], bpB);
                } else {
                    accA[r % 3] = fma2(cv, wpA[ci * 9 + 0 + kx], accA[r % 3]);
                    accB[r % 3] = fma2(cv, wpB[ci * 9 + 0 + kx], accB[r % 3]);
                }
            }
        }

        // output row y = r-2 complete for all 4 channels
        if (r >= 2) {
            const int yoff = (r - 2) * OW;
            float v0, v1, v2, v3;
            upk2(accA[(r - 2) % 3], v0, v1);
            upk2(accB[(r - 2) % 3], v2, v3);
            out0[0 * OH * OW + yoff] = hswish_relu(v0);
            out0[1 * OH * OW + yoff] = hswish_relu(v1);
            out0[2 * OH * OW + yoff] = hswish_relu(v2);
            out0[3 * OH * OW + yoff] = hswish_relu(v3);
        }
    }
}

extern "C" void kernel_launch(void* const* d_in, const int* in_sizes, int n_in,
                              void* d_out, int out_size) {
    const float* x = (const float*)d_in[0];
    const float* w = (const float*)d_in[1];
    const float* b = (const float*)d_in[2];
    float* out = (float*)d_out;

    const int N = in_sizes[0] / (CIN * HH * WW);   // 4096
    conv3x3_hswish_kernel<<<N, 128>>>(x, w, b, out);
}

// round 11
// speedup vs baseline: 2.4958x; 1.0973x over previous
#include <cuda_runtime.h>
#include <cstdint>

#define CIN 3
#define COUT 16
#define HH 32
#define WW 32
#define OH 30
#define OW 30

typedef unsigned long long u64;

// ---- f32x2 packed-math helpers (SASS FFMA2 via PTX only) ----
__device__ __forceinline__ u64 pk2(float a, float b) {
    u64 r; asm("mov.b64 %0, {%1, %2};" : "=l"(r) : "f"(a), "f"(b)); return r;
}
__device__ __forceinline__ u64 dup2(float a) {
    u64 r; asm("mov.b64 %0, {%1, %1};" : "=l"(r) : "f"(a)); return r;
}
__device__ __forceinline__ u64 fma2(u64 a, u64 b, u64 c) {
    u64 d; asm("fma.rn.f32x2 %0, %1, %2, %3;" : "=l"(d) : "l"(a), "l"(b), "l"(c)); return d;
}
__device__ __forceinline__ void upk2(u64 v, float& a, float& b) {
    asm("mov.b64 {%0, %1}, %2;" : "=f"(a), "=f"(b) : "l"(v));
}
// activation: relu(v) * min(v+3,6)/6 == max(v,0) * min(v/6+0.5, 1)
__device__ __forceinline__ float hswish_relu(float v) {
    return fmaxf(v, 0.0f) * fminf(fmaf(v, 1.0f / 6.0f, 0.5f), 1.0f);
}

// Direct conv v5 — occupancy build.
// Grid 8192: block b -> image b>>1, channel-half b&1. 128 threads = 4 warps;
// warp w -> channel pair c0 = (half*4 + w)*2. Lane = output column.
// 2ch/warp halves the weight register file vs R5 (54 vs 108 regs) so FIVE
// blocks fit per SM (20 warps, 5/SMSP) instead of 3 — the R5-R10 rounds showed
// the kernel is stall-bound (issue 44-47%) at 3 warps/SMSP, not pipe-bound.
// Hot loop = R5's validated streaming scheme: scalar LDS.32 prefetch one full
// row ahead (crossbar-safe), one dup2 temp per value, acc[y%3] rotation.
__global__ void __launch_bounds__(128, 5) conv3x3_hswish_kernel(
    const float* __restrict__ x,
    const float* __restrict__ wgt,
    const float* __restrict__ bias,
    float* __restrict__ out)
{
    __shared__ float s_in[CIN * HH * WW];   // 12 KB

    const int n    = blockIdx.x >> 1;
    const int half = blockIdx.x & 1;
    const int tid  = threadIdx.x;

    {   // coalesced image load: 768 float4 / 128 threads = 6 each
        const float4* src = reinterpret_cast<const float4*>(x + (size_t)n * (CIN * HH * WW));
        float4* dst = reinterpret_cast<float4*>(s_in);
        #pragma unroll
        for (int i = 0; i < 6; i++) dst[tid + i * 128] = src[tid + i * 128];
    }
    __syncthreads();

    const int warp = tid >> 5;
    const int lane = tid & 31;
    const int c0   = (half * 4 + warp) * 2;   // channel pair

    // packed weights: wp[ci*9 + ky*3 + kx] = {w[c0], w[c0+1]}
    u64 wp[27];
    #pragma unroll
    for (int t = 0; t < 27; t++)
        wp[t] = pk2(wgt[c0 * 27 + t], wgt[(c0 + 1) * 27 + t]);
    const u64 bp = pk2(bias[c0], bias[c0 + 1]);

    if (lane >= OW) return;   // barrier done; lanes 30/31 retire

    const float* base = s_in + lane;   // [ci*1024 + row*32 + kx]
    float* out0 = out + ((size_t)n * COUT + c0) * (OH * OW) + lane;

    // scalar double-buffered row window; parity compile-time (full unroll).
    float nb0[9], nb1[9];
    u64 acc[3];               // acc[y % 3] = accumulator for output row y

    #pragma unroll
    for (int ci = 0; ci < CIN; ci++)
        #pragma unroll
        for (int kx = 0; kx < 3; kx++)
            nb0[ci * 3 + kx] = base[ci * 1024 + kx];   // input row 0

    #pragma unroll
    for (int r = 0; r < 32; r++) {
        // prefetch input row r+1 into the other buffer (full-row distance)
        if (r < 31) {
            #pragma unroll
            for (int ci = 0; ci < CIN; ci++)
                #pragma unroll
                for (int kx = 0; kx < 3; kx++) {
                    float v = base[ci * 1024 + (r + 1) * 32 + kx];
                    if (r & 1) nb0[ci * 3 + kx] = v; else nb1[ci * 3 + kx] = v;
                }
        }

        if (r <= 29) acc[r % 3] = bp;

        #pragma unroll
        for (int t = 0; t < 9; t++) {
            const int ci = t / 3, kx = t % 3;
            const u64 dv = dup2((r & 1) ? nb1[t] : nb0[t]);  // one dup, 3 uses
            if (r >= 2)
                acc[(r - 2) % 3] = fma2(dv, wp[ci * 9 + 6 + kx], acc[(r - 2) % 3]);
            if (r >= 1 && r <= 30)
                acc[(r - 1) % 3] = fma2(dv, wp[ci * 9 + 3 + kx], acc[(r - 1) % 3]);
            if (r <= 29)
                acc[r % 3]       = fma2(dv, wp[ci * 9 + 0 + kx], acc[r % 3]);
        }

        // output row y = r-2 is complete
        if (r >= 2) {
            const int yoff = (r - 2) * OW;
            float v0, v1;
            upk2(acc[(r - 2) % 3], v0, v1);
            out0[yoff]           = hswish_relu(v0);
            out0[OH * OW + yoff] = hswish_relu(v1);
        }
    }
}

extern "C" void kernel_launch(void* const* d_in, const int* in_sizes, int n_in,
                              void* d_out, int out_size) {
    const float* x = (const float*)d_in[0];
    const float* w = (const float*)d_in[1];
    const float* b = (const float*)d_in[2];
    float* out = (float*)d_out;

    const int N = in_sizes[0] / (CIN * HH * WW);   // 4096
    conv3x3_hswish_kernel<<<N * 2, 128>>>(x, w, b, out);
}